// round 1
// baseline (speedup 1.0000x reference)
#include <cuda_runtime.h>
#include <cstdint>

#define B_   4
#define T_   2048
#define D_   2048
#define H_   16
#define DH_  128
#define M_   (B_ * T_)   // 8192

// Scratch: __device__ globals (allocation inside kernel_launch is forbidden).
// Q/K/V in [B,H,T,Dh] layout; attn output in [B,T,H*Dh] (= row-major [M_, D_]).
__device__ float g_q[16777216];
__device__ float g_k[16777216];
__device__ float g_v[16777216];
__device__ float g_attn[16777216];

// ---------------------------------------------------------------------------
// GEMM: C[m,n] = sum_k A[m,k] * W[n,k] + bias[n]
// A: [M_, D_] row-major, W: [N=D_, K=D_] row-major (torch Linear weight).
// scatter=1: write to [B,H,T,Dh] layout (for Q/K/V). scatter=0: row-major.
// 128x128 block tile, 256 threads, 8x8 micro-tile, BK=8.
// ---------------------------------------------------------------------------
__global__ __launch_bounds__(256, 2)
void gemm_bias_kernel(const float* __restrict__ A, const float* __restrict__ W,
                      const float* __restrict__ bias, float* __restrict__ C,
                      int scatter)
{
    __shared__ float As[8][132];   // [k][m], padded
    __shared__ float Bs[8][132];   // [k][n], padded

    const int tid  = threadIdx.x;
    const int tx   = tid & 15;
    const int ty   = tid >> 4;
    const int row0 = blockIdx.y * 128;
    const int col0 = blockIdx.x * 128;

    const int lrow = tid >> 1;           // 0..127
    const int lvec = (tid & 1) * 4;      // 0 or 4

    const float* Ap = A + (size_t)(row0 + lrow) * D_ + lvec;
    const float* Wp = W + (size_t)(col0 + lrow) * D_ + lvec;

    float acc[8][8];
#pragma unroll
    for (int i = 0; i < 8; i++)
#pragma unroll
        for (int j = 0; j < 8; j++) acc[i][j] = 0.0f;

    for (int k0 = 0; k0 < D_; k0 += 8) {
        const float4 a4 = *reinterpret_cast<const float4*>(Ap + k0);
        const float4 w4 = *reinterpret_cast<const float4*>(Wp + k0);
        __syncthreads();
        As[lvec + 0][lrow] = a4.x;
        As[lvec + 1][lrow] = a4.y;
        As[lvec + 2][lrow] = a4.z;
        As[lvec + 3][lrow] = a4.w;
        Bs[lvec + 0][lrow] = w4.x;
        Bs[lvec + 1][lrow] = w4.y;
        Bs[lvec + 2][lrow] = w4.z;
        Bs[lvec + 3][lrow] = w4.w;
        __syncthreads();
#pragma unroll
        for (int kk = 0; kk < 8; kk++) {
            const float4 a0 = *reinterpret_cast<const float4*>(&As[kk][ty * 4]);
            const float4 a1 = *reinterpret_cast<const float4*>(&As[kk][64 + ty * 4]);
            const float4 b0 = *reinterpret_cast<const float4*>(&Bs[kk][tx * 4]);
            const float4 b1 = *reinterpret_cast<const float4*>(&Bs[kk][64 + tx * 4]);
            const float a[8] = {a0.x, a0.y, a0.z, a0.w, a1.x, a1.y, a1.z, a1.w};
            const float b[8] = {b0.x, b0.y, b0.z, b0.w, b1.x, b1.y, b1.z, b1.w};
#pragma unroll
            for (int i = 0; i < 8; i++)
#pragma unroll
                for (int j = 0; j < 8; j++)
                    acc[i][j] = fmaf(a[i], b[j], acc[i][j]);
        }
    }

    const float4 bi0 = *reinterpret_cast<const float4*>(bias + col0 + tx * 4);
    const float4 bi1 = *reinterpret_cast<const float4*>(bias + col0 + 64 + tx * 4);
    const float bb[8] = {bi0.x, bi0.y, bi0.z, bi0.w, bi1.x, bi1.y, bi1.z, bi1.w};

#pragma unroll
    for (int i = 0; i < 8; i++) {
        const int m = row0 + ((i < 4) ? (ty * 4 + i) : (64 + ty * 4 + (i - 4)));
        const float4 o0 = make_float4(acc[i][0] + bb[0], acc[i][1] + bb[1],
                                      acc[i][2] + bb[2], acc[i][3] + bb[3]);
        const float4 o1 = make_float4(acc[i][4] + bb[4], acc[i][5] + bb[5],
                                      acc[i][6] + bb[6], acc[i][7] + bb[7]);
        if (scatter) {
            // [B,H,T,Dh]: b = m>>11, t = m&2047, h = col0>>7, d = col within block
            const size_t base =
                (((size_t)(m >> 11) * H_ + (size_t)(col0 >> 7)) * T_ + (size_t)(m & (T_ - 1))) * DH_;
            *reinterpret_cast<float4*>(C + base + tx * 4) = o0;
            *reinterpret_cast<float4*>(C + base + 64 + tx * 4) = o1;
        } else {
            float* cp = C + (size_t)m * D_ + col0;
            *reinterpret_cast<float4*>(cp + tx * 4) = o0;
            *reinterpret_cast<float4*>(cp + 64 + tx * 4) = o1;
        }
    }
}

// ---------------------------------------------------------------------------
// Flash attention (fp32, online softmax). One block = one (b,h) x 64 q-rows.
// Q/K stored k-major in smem ([k][row], stride 68) for conflict-free fragment
// loads; V natural ([kv][d], stride 132). P staged via smem for the PV GEMM.
// ---------------------------------------------------------------------------
#define ATTN_SMEM_FLOATS (128*68 + 128*68 + 64*132 + 64*68 + 64*17 + 64*3)
#define ATTN_SMEM_BYTES  (ATTN_SMEM_FLOATS * 4)

__global__ __launch_bounds__(256, 1)
void attn_kernel(const float* __restrict__ Q, const float* __restrict__ K,
                 const float* __restrict__ V, float* __restrict__ O)
{
    extern __shared__ float sm[];
    float* Qst = sm;                    // [128][68]  (k-major Q tile)
    float* Kst = Qst + 128 * 68;        // [128][68]  (k-major K tile)
    float* Vs  = Kst + 128 * 68;        // [64][132]  (natural V tile)
    float* Ps  = Vs  + 64 * 132;        // [64][68]   (probabilities)
    float* red = Ps  + 64 * 68;         // [64][17]   (reductions)
    float* mst = red + 64 * 17;         // [64] running max
    float* lst = mst + 64;              // [64] running sum
    float* alf = lst + 64;              // [64] rescale factor

    const int tid = threadIdx.x;
    const int tx  = tid & 15;           // 0..15
    const int ty  = tid >> 4;           // 0..15
    const int qt  = blockIdx.x;         // 0..31
    const int bh  = blockIdx.y;         // 0..63

    const float* Qg = Q + (size_t)bh * T_ * DH_ + (size_t)qt * 64 * DH_;
    const float* Kg = K + (size_t)bh * T_ * DH_;
    const float* Vg = V + (size_t)bh * T_ * DH_;

    // Load Q tile, transposed into [k][row]
    for (int i = tid; i < 64 * 32; i += 256) {
        const int r = i >> 5, v = i & 31;
        const float4 q4 = reinterpret_cast<const float4*>(Qg)[r * 32 + v];
        Qst[(4 * v + 0) * 68 + r] = q4.x;
        Qst[(4 * v + 1) * 68 + r] = q4.y;
        Qst[(4 * v + 2) * 68 + r] = q4.z;
        Qst[(4 * v + 3) * 68 + r] = q4.w;
    }
    if (tid < 64) { mst[tid] = -1e30f; lst[tid] = 0.0f; }

    float acc_o[4][8];
#pragma unroll
    for (int i = 0; i < 4; i++)
#pragma unroll
        for (int j = 0; j < 8; j++) acc_o[i][j] = 0.0f;

    __syncthreads();

    for (int kt = 0; kt < T_ / 64; kt++) {
        const float4* Kgt = reinterpret_cast<const float4*>(Kg + (size_t)kt * 64 * DH_);
        const float4* Vgt = reinterpret_cast<const float4*>(Vg + (size_t)kt * 64 * DH_);
        for (int i = tid; i < 64 * 32; i += 256) {
            const int r = i >> 5, v = i & 31;
            const float4 k4 = Kgt[r * 32 + v];
            Kst[(4 * v + 0) * 68 + r] = k4.x;
            Kst[(4 * v + 1) * 68 + r] = k4.y;
            Kst[(4 * v + 2) * 68 + r] = k4.z;
            Kst[(4 * v + 3) * 68 + r] = k4.w;
            reinterpret_cast<float4*>(Vs + r * 132)[v] = Vgt[r * 32 + v];
        }
        __syncthreads();

        // S = Q · K^T  (rows ty*4+i, cols tx*4+j)
        float accs[4][4];
#pragma unroll
        for (int i = 0; i < 4; i++)
#pragma unroll
            for (int j = 0; j < 4; j++) accs[i][j] = 0.0f;

#pragma unroll 8
        for (int kk = 0; kk < 128; kk++) {
            const float4 a = *reinterpret_cast<const float4*>(Qst + kk * 68 + ty * 4);
            const float4 b = *reinterpret_cast<const float4*>(Kst + kk * 68 + tx * 4);
            const float av[4] = {a.x, a.y, a.z, a.w};
            const float bv[4] = {b.x, b.y, b.z, b.w};
#pragma unroll
            for (int i = 0; i < 4; i++)
#pragma unroll
                for (int j = 0; j < 4; j++)
                    accs[i][j] = fmaf(av[i], bv[j], accs[i][j]);
        }

        const float sc = 0.08838834764831845f;  // 1/sqrt(128)
#pragma unroll
        for (int i = 0; i < 4; i++) {
            float lm = -1e30f;
#pragma unroll
            for (int j = 0; j < 4; j++) {
                accs[i][j] *= sc;
                lm = fmaxf(lm, accs[i][j]);
            }
            red[(ty * 4 + i) * 17 + tx] = lm;
        }
        __syncthreads();
        if (tid < 64) {
            float m = red[tid * 17];
            for (int t2 = 1; t2 < 16; t2++) m = fmaxf(m, red[tid * 17 + t2]);
            const float mo = mst[tid];
            const float mn = fmaxf(mo, m);
            mst[tid] = mn;
            alf[tid] = __expf(mo - mn);
        }
        __syncthreads();
#pragma unroll
        for (int i = 0; i < 4; i++) {
            const float mn = mst[ty * 4 + i];
            float4 p;
            p.x = __expf(accs[i][0] - mn);
            p.y = __expf(accs[i][1] - mn);
            p.z = __expf(accs[i][2] - mn);
            p.w = __expf(accs[i][3] - mn);
            *reinterpret_cast<float4*>(Ps + (ty * 4 + i) * 68 + tx * 4) = p;
            red[(ty * 4 + i) * 17 + tx] = p.x + p.y + p.z + p.w;
        }
        __syncthreads();
        if (tid < 64) {
            float s = 0.0f;
            for (int t2 = 0; t2 < 16; t2++) s += red[tid * 17 + t2];
            lst[tid] = alf[tid] * lst[tid] + s;
        }
        __syncthreads();

        // O = O*alpha + P·V  (rows ty*4+i, cols tx*4+j and 64+tx*4+j)
        float ar[4];
#pragma unroll
        for (int i = 0; i < 4; i++) ar[i] = alf[ty * 4 + i];
#pragma unroll
        for (int i = 0; i < 4; i++)
#pragma unroll
            for (int j = 0; j < 8; j++) acc_o[i][j] *= ar[i];

#pragma unroll 4
        for (int kv = 0; kv < 64; kv++) {
            const float4 b0 = *reinterpret_cast<const float4*>(Vs + kv * 132 + tx * 4);
            const float4 b1 = *reinterpret_cast<const float4*>(Vs + kv * 132 + 64 + tx * 4);
            const float bv[8] = {b0.x, b0.y, b0.z, b0.w, b1.x, b1.y, b1.z, b1.w};
            float av[4];
#pragma unroll
            for (int i = 0; i < 4; i++) av[i] = Ps[(ty * 4 + i) * 68 + kv];
#pragma unroll
            for (int i = 0; i < 4; i++)
#pragma unroll
                for (int j = 0; j < 8; j++)
                    acc_o[i][j] = fmaf(av[i], bv[j], acc_o[i][j]);
        }
        __syncthreads();
    }

    // Epilogue: divide by l, write to [B, T, H*Dh]
    const int b = bh >> 4, h = bh & 15;
#pragma unroll
    for (int i = 0; i < 4; i++) {
        const int t = qt * 64 + ty * 4 + i;
        const float inv = 1.0f / lst[ty * 4 + i];
        float* dst = O + (size_t)(b * T_ + t) * D_ + h * DH_;
        const float4 o0 = make_float4(acc_o[i][0] * inv, acc_o[i][1] * inv,
                                      acc_o[i][2] * inv, acc_o[i][3] * inv);
        const float4 o1 = make_float4(acc_o[i][4] * inv, acc_o[i][5] * inv,
                                      acc_o[i][6] * inv, acc_o[i][7] * inv);
        *reinterpret_cast<float4*>(dst + tx * 4) = o0;
        *reinterpret_cast<float4*>(dst + 64 + tx * 4) = o1;
    }
}

// ---------------------------------------------------------------------------
extern "C" void kernel_launch(void* const* d_in, const int* in_sizes, int n_in,
                              void* d_out, int out_size)
{
    const float* x  = (const float*)d_in[0];
    const float* Wq = (const float*)d_in[1];
    const float* bq = (const float*)d_in[2];
    const float* Wk = (const float*)d_in[3];
    const float* bk = (const float*)d_in[4];
    const float* Wv = (const float*)d_in[5];
    const float* bv = (const float*)d_in[6];
    const float* Wo = (const float*)d_in[7];
    const float* bo = (const float*)d_in[8];

    float *q, *k, *v, *attn;
    cudaGetSymbolAddress((void**)&q,    g_q);
    cudaGetSymbolAddress((void**)&k,    g_k);
    cudaGetSymbolAddress((void**)&v,    g_v);
    cudaGetSymbolAddress((void**)&attn, g_attn);

    cudaFuncSetAttribute(attn_kernel, cudaFuncAttributeMaxDynamicSharedMemorySize,
                         ATTN_SMEM_BYTES);

    const dim3 gb(D_ / 128, M_ / 128);   // (16, 64)
    gemm_bias_kernel<<<gb, 256>>>(x, Wq, bq, q, 1);
    gemm_bias_kernel<<<gb, 256>>>(x, Wk, bk, k, 1);
    gemm_bias_kernel<<<gb, 256>>>(x, Wv, bv, v, 1);
    attn_kernel<<<dim3(T_ / 64, B_ * H_), 256, ATTN_SMEM_BYTES>>>(q, k, v, attn);
    gemm_bias_kernel<<<gb, 256>>>(attn, Wo, bo, (float*)d_out, 0);
}

// round 4
// speedup vs baseline: 1.6293x; 1.6293x over previous
#include <cuda_runtime.h>
#include <cuda_bf16.h>
#include <cstdint>

#define B_   4
#define T_   2048
#define D_   2048
#define H_   16
#define DH_  128
#define M_   8192

// ---------------- scratch (__device__ globals; no allocs allowed) ----------
__device__ float g_q[16777216];
__device__ float g_k[16777216];
__device__ float g_v[16777216];
__device__ __nv_bfloat16 g_xh[16777216];
__device__ __nv_bfloat16 g_xl[16777216];
__device__ __nv_bfloat16 g_wh[16777216];   // Wq|Wk|Wv|Wo, 4M elems each
__device__ __nv_bfloat16 g_wl[16777216];
__device__ __nv_bfloat16 g_ah[16777216];   // attention output hi/lo
__device__ __nv_bfloat16 g_al[16777216];

// ---------------- PTX helpers (baseline ISA only; no tcgen05) --------------
__device__ __forceinline__ uint32_t smem_u32(const void* p) {
    uint32_t a;
    asm("{ .reg .u64 t; cvta.to.shared.u64 t, %1; cvt.u32.u64 %0, t; }" : "=r"(a) : "l"(p));
    return a;
}
__device__ __forceinline__ void cp16(uint32_t dst, const void* src) {
    asm volatile("cp.async.cg.shared.global [%0], [%1], 16;" :: "r"(dst), "l"(src) : "memory");
}
__device__ __forceinline__ void cp_commit() { asm volatile("cp.async.commit_group;" ::: "memory"); }
template <int N> __device__ __forceinline__ void cp_wait() {
    asm volatile("cp.async.wait_group %0;" :: "n"(N) : "memory");
}
__device__ __forceinline__ uint32_t sw128(uint32_t off) { return off ^ ((off >> 3) & 0x70); }

__device__ __forceinline__ void ldm_x4(uint32_t* r, uint32_t addr) {
    asm volatile("ldmatrix.sync.aligned.m8n8.x4.shared.b16 {%0,%1,%2,%3}, [%4];"
                 : "=r"(r[0]), "=r"(r[1]), "=r"(r[2]), "=r"(r[3]) : "r"(addr));
}
__device__ __forceinline__ void mma_16816(float* d, const uint32_t* a, const uint32_t* b) {
    asm volatile("mma.sync.aligned.m16n8k16.row.col.f32.bf16.bf16.f32 "
                 "{%0,%1,%2,%3}, {%4,%5,%6,%7}, {%8,%9}, {%0,%1,%2,%3};"
                 : "+f"(d[0]), "+f"(d[1]), "+f"(d[2]), "+f"(d[3])
                 : "r"(a[0]), "r"(a[1]), "r"(a[2]), "r"(a[3]), "r"(b[0]), "r"(b[1]));
}

// ---------------- fp32 -> bf16 hi/lo split --------------------------------
__global__ void convert_hilo(const float4* __restrict__ in,
                             __nv_bfloat162* __restrict__ hi,
                             __nv_bfloat162* __restrict__ lo, int n4)
{
    int i = blockIdx.x * 256 + threadIdx.x;
    if (i >= n4) return;
    float4 v = in[i];
    __nv_bfloat16 hx = __float2bfloat16_rn(v.x);
    __nv_bfloat16 hy = __float2bfloat16_rn(v.y);
    __nv_bfloat16 hz = __float2bfloat16_rn(v.z);
    __nv_bfloat16 hw = __float2bfloat16_rn(v.w);
    __nv_bfloat16 lx = __float2bfloat16_rn(v.x - __bfloat162float(hx));
    __nv_bfloat16 ly = __float2bfloat16_rn(v.y - __bfloat162float(hy));
    __nv_bfloat16 lz = __float2bfloat16_rn(v.z - __bfloat162float(hz));
    __nv_bfloat16 lw = __float2bfloat16_rn(v.w - __bfloat162float(hw));
    hi[2 * i + 0] = __halves2bfloat162(hx, hy);
    hi[2 * i + 1] = __halves2bfloat162(hz, hw);
    lo[2 * i + 0] = __halves2bfloat162(lx, ly);
    lo[2 * i + 1] = __halves2bfloat162(lz, lw);
}

// ---------------- mma.sync split-bf16 GEMM --------------------------------
// C[m,n] = sum_k A[m,k]*W[n,k] + bias[n], via AhWh + AhWl + AlWh (fp32 acc).
// CTA: 128x128 tile, 8 warps (2m x 4n), warp tile 64x32.
// K-chunks of 64 (rows = 128B, SW128). 2-stage cp.async pipeline.
#define STAGE_BYTES 65536
#define SM_AH 0
#define SM_AL 16384
#define SM_BH 32768
#define SM_BL 49152
#define GEMM_DYN (2 * STAGE_BYTES + 1024)
#define NCHUNK 32

__device__ __forceinline__ void load_chunk(uint32_t base, int st,
    const __nv_bfloat16* __restrict__ Agh, const __nv_bfloat16* __restrict__ Agl,
    const __nv_bfloat16* __restrict__ Bgh, const __nv_bfloat16* __restrict__ Bgl,
    int chunk, int tid)
{
    const uint32_t sb = base + st * STAGE_BYTES;
    const int koff = chunk * 64;
#pragma unroll
    for (int j = 0; j < 4; j++) {
        const int id = tid + j * 256;            // 0..1023
        const int r = id >> 3, c = id & 7;       // row 0..127, 16B slot 0..7
        const uint32_t soff = sw128((uint32_t)(r * 128 + c * 16));
        const size_t goff = (size_t)r * D_ + koff + c * 8;
        cp16(sb + SM_AH + soff, Agh + goff);
        cp16(sb + SM_AL + soff, Agl + goff);
        cp16(sb + SM_BH + soff, Bgh + goff);
        cp16(sb + SM_BL + soff, Bgl + goff);
    }
}

__global__ __launch_bounds__(256, 1)
void gemm_mma(const __nv_bfloat16* __restrict__ Ah, const __nv_bfloat16* __restrict__ Al,
              const __nv_bfloat16* __restrict__ Bh, const __nv_bfloat16* __restrict__ Bl,
              const float* __restrict__ bias, float* __restrict__ C, int scatter)
{
    extern __shared__ char dyn[];
    uint32_t base = smem_u32(dyn);
    base = (base + 1023u) & ~1023u;

    const int tid = threadIdx.x;
    const int wid = tid >> 5;
    const int l   = tid & 31;
    const int wm  = wid >> 2;        // 0..1  (64-row m slab)
    const int wn  = wid & 3;         // 0..3  (32-col n slab)
    const int bx = blockIdx.x, by = blockIdx.y;

    const __nv_bfloat16* Agh = Ah + (size_t)by * 128 * D_;
    const __nv_bfloat16* Agl = Al + (size_t)by * 128 * D_;
    const __nv_bfloat16* Bgh = Bh + (size_t)bx * 128 * D_;
    const __nv_bfloat16* Bgl = Bl + (size_t)bx * 128 * D_;

    float acc[4][4][4];
#pragma unroll
    for (int mi = 0; mi < 4; mi++)
#pragma unroll
        for (int ni = 0; ni < 4; ni++)
#pragma unroll
            for (int j = 0; j < 4; j++) acc[mi][ni][j] = 0.0f;

    // ldmatrix address components (within a 128-row x 128B tile)
    const int a_row = wm * 64 + (l & 15);        // + mi*16
    const int a_kb  = (l >> 4) * 16;             // + ks*32
    const int b_row = wn * 32 + (l & 7) + ((l >> 4) & 1) * 8;  // + nb*16
    const int b_kb  = ((l >> 3) & 1) * 16;       // + ks*32

    load_chunk(base, 0, Agh, Agl, Bgh, Bgl, 0, tid); cp_commit();
    load_chunk(base, 1, Agh, Agl, Bgh, Bgl, 1, tid); cp_commit();

    for (int i = 0; i < NCHUNK; i++) {
        const int st = i & 1;
        if (i < NCHUNK - 1) cp_wait<1>(); else cp_wait<0>();
        __syncthreads();

        const uint32_t sb = base + st * STAGE_BYTES;
#pragma unroll
        for (int ks = 0; ks < 4; ks++) {
            uint32_t ah[4][4], al[4][4], bh[2][4], bl[2][4];
#pragma unroll
            for (int mi = 0; mi < 4; mi++) {
                const uint32_t off = sw128((uint32_t)((a_row + mi * 16) * 128 + ks * 32 + a_kb));
                ldm_x4(ah[mi], sb + SM_AH + off);
                ldm_x4(al[mi], sb + SM_AL + off);
            }
#pragma unroll
            for (int nb = 0; nb < 2; nb++) {
                const uint32_t off = sw128((uint32_t)((b_row + nb * 16) * 128 + ks * 32 + b_kb));
                ldm_x4(bh[nb], sb + SM_BH + off);
                ldm_x4(bl[nb], sb + SM_BL + off);
            }
#pragma unroll
            for (int mi = 0; mi < 4; mi++)
#pragma unroll
                for (int ni = 0; ni < 4; ni++) {
                    const uint32_t* ph = &bh[ni >> 1][(ni & 1) * 2];
                    const uint32_t* pl = &bl[ni >> 1][(ni & 1) * 2];
                    mma_16816(acc[mi][ni], ah[mi], ph);
                    mma_16816(acc[mi][ni], ah[mi], pl);
                    mma_16816(acc[mi][ni], al[mi], ph);
                }
        }
        __syncthreads();
        if (i + 2 < NCHUNK) {
            load_chunk(base, st, Agh, Agl, Bgh, Bgl, i + 2, tid);
            cp_commit();
        }
    }

    // Epilogue: d0:(r, c) d1:(r, c+1) d2:(r+8, c) d3:(r+8, c+1); r=l>>2, c=(l&3)*2
#pragma unroll
    for (int mi = 0; mi < 4; mi++) {
#pragma unroll
        for (int ni = 0; ni < 4; ni++) {
            const int n = bx * 128 + wn * 32 + ni * 8 + (l & 3) * 2;
            const float2 bv = *reinterpret_cast<const float2*>(bias + n);
            const int m0 = by * 128 + wm * 64 + mi * 16 + (l >> 2);
#pragma unroll
            for (int half = 0; half < 2; half++) {
                const int m = m0 + half * 8;
                float2 o;
                o.x = acc[mi][ni][half * 2 + 0] + bv.x;
                o.y = acc[mi][ni][half * 2 + 1] + bv.y;
                float* dst;
                if (scatter) {
                    const int h = n >> 7, d0 = n & 127;
                    dst = C + (((size_t)(m >> 11) * H_ + h) * T_ + (m & (T_ - 1))) * DH_ + d0;
                } else {
                    dst = C + (size_t)m * D_ + n;
                }
                *reinterpret_cast<float2*>(dst) = o;
            }
        }
    }
}

// ---------------- fp32 flash attention (unchanged; bf16 hi/lo out) ---------
#define ATTN_SMEM_FLOATS (128*68 + 128*68 + 64*132 + 64*68 + 64*17 + 64*3)
#define ATTN_SMEM_BYTES  (ATTN_SMEM_FLOATS * 4)

__global__ __launch_bounds__(256, 1)
void attn_kernel(const float* __restrict__ Q, const float* __restrict__ K,
                 const float* __restrict__ V,
                 __nv_bfloat16* __restrict__ Oh, __nv_bfloat16* __restrict__ Ol)
{
    extern __shared__ float sm[];
    float* Qst = sm;
    float* Kst = Qst + 128 * 68;
    float* Vs  = Kst + 128 * 68;
    float* Ps  = Vs  + 64 * 132;
    float* red = Ps  + 64 * 68;
    float* mst = red + 64 * 17;
    float* lst = mst + 64;
    float* alf = lst + 64;

    const int tid = threadIdx.x;
    const int tx  = tid & 15;
    const int ty  = tid >> 4;
    const int qt  = blockIdx.x;
    const int bh  = blockIdx.y;

    const float* Qg = Q + (size_t)bh * T_ * DH_ + (size_t)qt * 64 * DH_;
    const float* Kg = K + (size_t)bh * T_ * DH_;
    const float* Vg = V + (size_t)bh * T_ * DH_;

    for (int i = tid; i < 64 * 32; i += 256) {
        const int r = i >> 5, v = i & 31;
        const float4 q4 = reinterpret_cast<const float4*>(Qg)[r * 32 + v];
        Qst[(4 * v + 0) * 68 + r] = q4.x;
        Qst[(4 * v + 1) * 68 + r] = q4.y;
        Qst[(4 * v + 2) * 68 + r] = q4.z;
        Qst[(4 * v + 3) * 68 + r] = q4.w;
    }
    if (tid < 64) { mst[tid] = -1e30f; lst[tid] = 0.0f; }

    float acc_o[4][8];
#pragma unroll
    for (int i = 0; i < 4; i++)
#pragma unroll
        for (int j = 0; j < 8; j++) acc_o[i][j] = 0.0f;

    __syncthreads();

    for (int kt = 0; kt < T_ / 64; kt++) {
        const float4* Kgt = reinterpret_cast<const float4*>(Kg + (size_t)kt * 64 * DH_);
        const float4* Vgt = reinterpret_cast<const float4*>(Vg + (size_t)kt * 64 * DH_);
        for (int i = tid; i < 64 * 32; i += 256) {
            const int r = i >> 5, v = i & 31;
            const float4 k4 = Kgt[r * 32 + v];
            Kst[(4 * v + 0) * 68 + r] = k4.x;
            Kst[(4 * v + 1) * 68 + r] = k4.y;
            Kst[(4 * v + 2) * 68 + r] = k4.z;
            Kst[(4 * v + 3) * 68 + r] = k4.w;
            reinterpret_cast<float4*>(Vs + r * 132)[v] = Vgt[r * 32 + v];
        }
        __syncthreads();

        float accs[4][4];
#pragma unroll
        for (int i = 0; i < 4; i++)
#pragma unroll
            for (int j = 0; j < 4; j++) accs[i][j] = 0.0f;

#pragma unroll 8
        for (int kk = 0; kk < 128; kk++) {
            const float4 a = *reinterpret_cast<const float4*>(Qst + kk * 68 + ty * 4);
            const float4 b = *reinterpret_cast<const float4*>(Kst + kk * 68 + tx * 4);
            const float av[4] = {a.x, a.y, a.z, a.w};
            const float bv[4] = {b.x, b.y, b.z, b.w};
#pragma unroll
            for (int i = 0; i < 4; i++)
#pragma unroll
                for (int j = 0; j < 4; j++)
                    accs[i][j] = fmaf(av[i], bv[j], accs[i][j]);
        }

        const float sc = 0.08838834764831845f;
#pragma unroll
        for (int i = 0; i < 4; i++) {
            float lm = -1e30f;
#pragma unroll
            for (int j = 0; j < 4; j++) {
                accs[i][j] *= sc;
                lm = fmaxf(lm, accs[i][j]);
            }
            red[(ty * 4 + i) * 17 + tx] = lm;
        }
        __syncthreads();
        if (tid < 64) {
            float m = red[tid * 17];
            for (int t2 = 1; t2 < 16; t2++) m = fmaxf(m, red[tid * 17 + t2]);
            const float mo = mst[tid];
            const float mn = fmaxf(mo, m);
            mst[tid] = mn;
            alf[tid] = __expf(mo - mn);
        }
        __syncthreads();
#pragma unroll
        for (int i = 0; i < 4; i++) {
            const float mn = mst[ty * 4 + i];
            float4 p;
            p.x = __expf(accs[i][0] - mn);
            p.y = __expf(accs[i][1] - mn);
            p.z = __expf(accs[i][2] - mn);
            p.w = __expf(accs[i][3] - mn);
            *reinterpret_cast<float4*>(Ps + (ty * 4 + i) * 68 + tx * 4) = p;
            red[(ty * 4 + i) * 17 + tx] = p.x + p.y + p.z + p.w;
        }
        __syncthreads();
        if (tid < 64) {
            float s = 0.0f;
            for (int t2 = 0; t2 < 16; t2++) s += red[tid * 17 + t2];
            lst[tid] = alf[tid] * lst[tid] + s;
        }
        __syncthreads();

        float ar[4];
#pragma unroll
        for (int i = 0; i < 4; i++) ar[i] = alf[ty * 4 + i];
#pragma unroll
        for (int i = 0; i < 4; i++)
#pragma unroll
            for (int j = 0; j < 8; j++) acc_o[i][j] *= ar[i];

#pragma unroll 4
        for (int kv = 0; kv < 64; kv++) {
            const float4 b0 = *reinterpret_cast<const float4*>(Vs + kv * 132 + tx * 4);
            const float4 b1 = *reinterpret_cast<const float4*>(Vs + kv * 132 + 64 + tx * 4);
            const float bv[8] = {b0.x, b0.y, b0.z, b0.w, b1.x, b1.y, b1.z, b1.w};
            float av[4];
#pragma unroll
            for (int i = 0; i < 4; i++) av[i] = Ps[(ty * 4 + i) * 68 + kv];
#pragma unroll
            for (int i = 0; i < 4; i++)
#pragma unroll
                for (int j = 0; j < 8; j++)
                    acc_o[i][j] = fmaf(av[i], bv[j], acc_o[i][j]);
        }
        __syncthreads();
    }

    const int b = bh >> 4, h = bh & 15;
#pragma unroll
    for (int i = 0; i < 4; i++) {
        const int t = qt * 64 + ty * 4 + i;
        const float inv = 1.0f / lst[ty * 4 + i];
        const size_t rowbase = ((size_t)(b * T_ + t)) * D_ + h * DH_;
        float ov[8];
#pragma unroll
        for (int j = 0; j < 8; j++) ov[j] = acc_o[i][j] * inv;
#pragma unroll
        for (int half = 0; half < 2; half++) {
            const size_t off = rowbase + half * 64 + tx * 4;
            __nv_bfloat16 h0 = __float2bfloat16_rn(ov[half * 4 + 0]);
            __nv_bfloat16 h1 = __float2bfloat16_rn(ov[half * 4 + 1]);
            __nv_bfloat16 h2 = __float2bfloat16_rn(ov[half * 4 + 2]);
            __nv_bfloat16 h3 = __float2bfloat16_rn(ov[half * 4 + 3]);
            __nv_bfloat16 l0 = __float2bfloat16_rn(ov[half * 4 + 0] - __bfloat162float(h0));
            __nv_bfloat16 l1 = __float2bfloat16_rn(ov[half * 4 + 1] - __bfloat162float(h1));
            __nv_bfloat16 l2 = __float2bfloat16_rn(ov[half * 4 + 2] - __bfloat162float(h2));
            __nv_bfloat16 l3 = __float2bfloat16_rn(ov[half * 4 + 3] - __bfloat162float(h3));
            __nv_bfloat162* dh = reinterpret_cast<__nv_bfloat162*>(Oh + off);
            __nv_bfloat162* dl = reinterpret_cast<__nv_bfloat162*>(Ol + off);
            dh[0] = __halves2bfloat162(h0, h1);
            dh[1] = __halves2bfloat162(h2, h3);
            dl[0] = __halves2bfloat162(l0, l1);
            dl[1] = __halves2bfloat162(l2, l3);
        }
    }
}

// ---------------------------------------------------------------------------
extern "C" void kernel_launch(void* const* d_in, const int* in_sizes, int n_in,
                              void* d_out, int out_size)
{
    const float* x  = (const float*)d_in[0];
    const float* Wq = (const float*)d_in[1];
    const float* bq = (const float*)d_in[2];
    const float* Wk = (const float*)d_in[3];
    const float* bk = (const float*)d_in[4];
    const float* Wv = (const float*)d_in[5];
    const float* bv = (const float*)d_in[6];
    const float* Wo = (const float*)d_in[7];
    const float* bo = (const float*)d_in[8];

    float *q, *k, *v;
    __nv_bfloat16 *xh, *xl, *wh, *wl, *ah, *al;
    cudaGetSymbolAddress((void**)&q,  g_q);
    cudaGetSymbolAddress((void**)&k,  g_k);
    cudaGetSymbolAddress((void**)&v,  g_v);
    cudaGetSymbolAddress((void**)&xh, g_xh);
    cudaGetSymbolAddress((void**)&xl, g_xl);
    cudaGetSymbolAddress((void**)&wh, g_wh);
    cudaGetSymbolAddress((void**)&wl, g_wl);
    cudaGetSymbolAddress((void**)&ah, g_ah);
    cudaGetSymbolAddress((void**)&al, g_al);

    cudaFuncSetAttribute(gemm_mma, cudaFuncAttributeMaxDynamicSharedMemorySize, GEMM_DYN);
    cudaFuncSetAttribute(attn_kernel, cudaFuncAttributeMaxDynamicSharedMemorySize,
                         ATTN_SMEM_BYTES);

    convert_hilo<<<16384, 256>>>((const float4*)x, (__nv_bfloat162*)xh,
                                 (__nv_bfloat162*)xl, 4194304);
    convert_hilo<<<4096, 256>>>((const float4*)Wq, (__nv_bfloat162*)(wh + 0),
                                (__nv_bfloat162*)(wl + 0), 1048576);
    convert_hilo<<<4096, 256>>>((const float4*)Wk, (__nv_bfloat162*)(wh + 4194304),
                                (__nv_bfloat162*)(wl + 4194304), 1048576);
    convert_hilo<<<4096, 256>>>((const float4*)Wv, (__nv_bfloat162*)(wh + 8388608),
                                (__nv_bfloat162*)(wl + 8388608), 1048576);
    convert_hilo<<<4096, 256>>>((const float4*)Wo, (__nv_bfloat162*)(wh + 12582912),
                                (__nv_bfloat162*)(wl + 12582912), 1048576);

    const dim3 gg(D_ / 128, M_ / 128);   // (16, 64)
    gemm_mma<<<gg, 256, GEMM_DYN>>>(xh, xl, wh + 0,        wl + 0,        bq, q, 1);
    gemm_mma<<<gg, 256, GEMM_DYN>>>(xh, xl, wh + 4194304,  wl + 4194304,  bk, k, 1);
    gemm_mma<<<gg, 256, GEMM_DYN>>>(xh, xl, wh + 8388608,  wl + 8388608,  bv, v, 1);

    attn_kernel<<<dim3(T_ / 64, B_ * H_), 256, ATTN_SMEM_BYTES>>>(q, k, v, ah, al);

    gemm_mma<<<gg, 256, GEMM_DYN>>>(ah, al, wh + 12582912, wl + 12582912, bo,
                                    (float*)d_out, 0);
}